// round 2
// baseline (speedup 1.0000x reference)
#include <cuda_runtime.h>

// Shape fixed by the reference
#define B_   8
#define T_   4096
#define D_   1024
#define L_   8                 // timesteps per chunk (held in registers)
#define NC_  (T_ / L_)         // 512 chunks per batch row
#define TPB  256               // 256 thr x float4 = D
#define NBLK (B_ * NC_)        // 4096 work items

// Decoupled-lookback state (zero-init at load; reset kernel re-zeros flags/ticket)
__device__ float    g_A[NBLK * D_];     // 16 MB  chunk aggregate: prod(a)
__device__ float    g_U[NBLK * D_];     // 16 MB  chunk aggregate: zero-init scan tail
__device__ float    g_X[NBLK * D_];     // 16 MB  inclusive state after chunk
__device__ unsigned g_flag[NBLK];       // 0 = invalid, 1 = aggregate, 2 = inclusive
__device__ unsigned g_ticket;

__device__ __forceinline__ float4 f4_fma(float4 a, float4 x, float4 u) {
    float4 r;
    r.x = fmaf(a.x, x.x, u.x); r.y = fmaf(a.y, x.y, u.y);
    r.z = fmaf(a.z, x.z, u.z); r.w = fmaf(a.w, x.w, u.w);
    return r;
}
__device__ __forceinline__ float4 f4_mul(float4 a, float4 b) {
    float4 r; r.x = a.x*b.x; r.y = a.y*b.y; r.z = a.z*b.z; r.w = a.w*b.w; return r;
}
__device__ __forceinline__ unsigned ld_acq(const unsigned* p) {
    unsigned v;
    asm volatile("ld.global.acquire.gpu.b32 %0, [%1];" : "=r"(v) : "l"(p));
    return v;
}
__device__ __forceinline__ void st_rel(unsigned* p, unsigned v) {
    asm volatile("st.global.release.gpu.b32 [%0], %1;" :: "l"(p), "r"(v));
}

__global__ void k_reset() {
    int i = blockIdx.x * blockDim.x + threadIdx.x;
    if (i < NBLK) g_flag[i] = 0u;
    if (i == 0) g_ticket = 0u;
}

__global__ void __launch_bounds__(TPB, 2)
k_scan_lookback(const float* __restrict__ a,
                const float* __restrict__ u,
                const float* __restrict__ x0,
                float* __restrict__ out)
{
    __shared__ unsigned sh_vid;
    __shared__ unsigned sh_flag;
    const int tid = threadIdx.x;

    if (tid == 0) sh_vid = atomicAdd(&g_ticket, 1u);
    __syncthreads();
    const unsigned vid = sh_vid;
    const int b = vid & (B_ - 1);     // chunk order within b increases with ticket
    const int c = (int)(vid >> 3);
    const int d = tid * 4;

    const long base = (((long)b * T_ + (long)c * L_) * D_ + d) >> 2;  // float4 units
    const float4* __restrict__ ap = reinterpret_cast<const float4*>(a) + base;
    const float4* __restrict__ up = reinterpret_cast<const float4*>(u) + base;

    // ---- Phase 1: burst-load chunk into registers (16 independent loads) ----
    float4 av[L_], uv[L_];
    #pragma unroll
    for (int t = 0; t < L_; ++t) {
        av[t] = ap[(long)t * (D_ / 4)];
        uv[t] = up[(long)t * (D_ / 4)];
    }
    if (c == 0) {  // fold x0 into u at global t=0
        float4 x0v = reinterpret_cast<const float4*>(x0)[(b * D_ + d) >> 2];
        uv[0] = f4_fma(av[0], x0v, uv[0]);
    }

    // Local chunk aggregate: A = prod a, U = scan with zero carry
    float4 A = av[0], U = uv[0];
    #pragma unroll
    for (int t = 1; t < L_; ++t) {
        U = f4_fma(av[t], U, uv[t]);
        A = f4_mul(A, av[t]);
    }

    float4* gA4 = reinterpret_cast<float4*>(g_A);
    float4* gU4 = reinterpret_cast<float4*>(g_U);
    float4* gX4 = reinterpret_cast<float4*>(g_X);
    const int si = ((b * NC_ + c) * D_ + d) >> 2;

    float4 x_in = make_float4(0.f, 0.f, 0.f, 0.f);

    if (c == 0) {
        // Inclusive known immediately
        gX4[si] = U;
        __threadfence();
        __syncthreads();
        if (tid == 0) st_rel(&g_flag[b * NC_], 2u);
    } else {
        // Publish aggregate ASAP so successors can make progress
        gA4[si] = A;
        gU4[si] = U;
        __threadfence();
        __syncthreads();
        if (tid == 0) st_rel(&g_flag[b * NC_ + c], 1u);

        // ---- Phase 2: decoupled lookback ----
        float4 As = make_float4(1.f, 1.f, 1.f, 1.f);
        float4 Us = make_float4(0.f, 0.f, 0.f, 0.f);
        int p = c - 1;
        for (;;) {
            if (tid == 0) {
                unsigned f;
                while ((f = ld_acq(&g_flag[b * NC_ + p])) == 0u) { /* spin */ }
                sh_flag = f;
            }
            __syncthreads();
            const unsigned f = sh_flag;
            __syncthreads();  // sh_flag safe for next iteration
            const int pi = ((b * NC_ + p) * D_ + d) >> 2;
            if (f == 2u) {
                float4 Xp = gX4[pi];
                x_in = f4_fma(As, Xp, Us);   // carry into this chunk
                break;
            } else {
                float4 Ap = gA4[pi];
                float4 Up = gU4[pi];
                Us = f4_fma(As, Up, Us);     // prepend chunk p to segment
                As = f4_mul(As, Ap);
                --p;
            }
        }

        // ---- Phase 3: publish inclusive ----
        float4 xo = f4_fma(A, x_in, U);
        gX4[si] = xo;
        __threadfence();
        __syncthreads();
        if (tid == 0) st_rel(&g_flag[b * NC_ + c], 2u);
    }

    // ---- Phase 4: materialize outputs from registers ----
    float4* __restrict__ op = reinterpret_cast<float4*>(out) + base;
    float4 x = x_in;
    #pragma unroll
    for (int t = 0; t < L_; ++t) {
        x = f4_fma(av[t], x, uv[t]);
        op[(long)t * (D_ / 4)] = x;
    }
}

extern "C" void kernel_launch(void* const* d_in, const int* in_sizes, int n_in,
                              void* d_out, int out_size) {
    const float* x0 = (const float*)d_in[0];
    const float* a  = (const float*)d_in[1];
    const float* u  = (const float*)d_in[2];
    float* out = (float*)d_out;

    k_reset<<<(NBLK + 255) / 256, 256>>>();
    k_scan_lookback<<<NBLK, TPB>>>(a, u, x0, out);
}

// round 3
// speedup vs baseline: 1.6302x; 1.6302x over previous
#include <cuda_runtime.h>

// Shape fixed by the reference
#define B_   8
#define T_   4096
#define D_   1024
#define L_   16                // timesteps per chunk (streamed, not register-held)
#define NC_  (T_ / L_)         // 256 chunks per batch row
#define TPB  256               // 256 thr x float4 = D
#define NBLK (B_ * NC_)        // 2048 blocks
#define LB_W 8                 // lookback batch width

// Decoupled-lookback state (8 MB each)
__device__ float    g_A[NBLK * D_];   // chunk aggregate: prod(a)
__device__ float    g_U[NBLK * D_];   // chunk aggregate: zero-init scan tail
__device__ float    g_X[NBLK * D_];   // inclusive state after chunk
__device__ unsigned g_flag[NBLK];     // 0=invalid, 1=aggregate, 2=inclusive
__device__ unsigned g_ticket;

__device__ __forceinline__ float4 f4_fma(float4 a, float4 x, float4 u) {
    float4 r;
    r.x = fmaf(a.x, x.x, u.x); r.y = fmaf(a.y, x.y, u.y);
    r.z = fmaf(a.z, x.z, u.z); r.w = fmaf(a.w, x.w, u.w);
    return r;
}
__device__ __forceinline__ float4 f4_mul(float4 a, float4 b) {
    float4 r; r.x = a.x*b.x; r.y = a.y*b.y; r.z = a.z*b.z; r.w = a.w*b.w; return r;
}
__device__ __forceinline__ unsigned ld_acq(const unsigned* p) {
    unsigned v;
    asm volatile("ld.global.acquire.gpu.b32 %0, [%1];" : "=r"(v) : "l"(p));
    return v;
}
__device__ __forceinline__ void st_rel(unsigned* p, unsigned v) {
    asm volatile("st.global.release.gpu.b32 [%0], %1;" :: "l"(p), "r"(v));
}

__global__ void k_reset() {
    int i = blockIdx.x * blockDim.x + threadIdx.x;
    if (i < NBLK) g_flag[i] = 0u;
    if (i == 0) g_ticket = 0u;
}

__global__ void __launch_bounds__(TPB)
k_scan(const float* __restrict__ a,
       const float* __restrict__ u,
       const float* __restrict__ x0,
       float* __restrict__ out)
{
    __shared__ unsigned sh_vid;
    __shared__ int sh_n;
    __shared__ int sh_inc;
    const int tid = threadIdx.x;

    if (tid == 0) sh_vid = atomicAdd(&g_ticket, 1u);
    __syncthreads();
    const unsigned vid = sh_vid;
    const int b = vid & (B_ - 1);         // round-robin b: all 8 chains progress evenly
    const int c = (int)(vid >> 3);
    const int d = tid * 4;

    const long base = (((long)b * T_ + (long)c * L_) * D_ + d) >> 2;  // float4 units
    const float4* __restrict__ ap = reinterpret_cast<const float4*>(a) + base;
    const float4* __restrict__ up = reinterpret_cast<const float4*>(u) + base;

    // ---- Phase 1: stream chunk once, compute aggregate (A = prod a, U = zero-carry scan)
    float4 A, U;
    {
        float4 av0 = ap[0];
        float4 uv0 = up[0];
        if (c == 0) {
            float4 x0v = reinterpret_cast<const float4*>(x0)[(b * D_ + d) >> 2];
            uv0 = f4_fma(av0, x0v, uv0);
        }
        A = av0; U = uv0;
        #pragma unroll
        for (int t = 1; t < L_; ++t) {
            float4 av = ap[(long)t * (D_ / 4)];
            float4 uv = up[(long)t * (D_ / 4)];
            U = f4_fma(av, U, uv);
            A = f4_mul(A, av);
        }
    }

    float4* gA4 = reinterpret_cast<float4*>(g_A);
    float4* gU4 = reinterpret_cast<float4*>(g_U);
    float4* gX4 = reinterpret_cast<float4*>(g_X);
    const int si = ((b * NC_ + c) * D_ + d) >> 2;

    float4 x_in = make_float4(0.f, 0.f, 0.f, 0.f);

    if (c == 0) {
        gX4[si] = U;                      // inclusive known immediately
        __syncthreads();
        if (tid == 0) { __threadfence(); st_rel(&g_flag[0 + b * NC_], 2u); }
    } else {
        // publish aggregate ASAP
        gA4[si] = A;
        gU4[si] = U;
        __syncthreads();
        if (tid == 0) { __threadfence(); st_rel(&g_flag[b * NC_ + c], 1u); }

        // ---- Phase 2: batched decoupled lookback (LB_W predecessors per round)
        float4 As = make_float4(1.f, 1.f, 1.f, 1.f);
        float4 Us = make_float4(0.f, 0.f, 0.f, 0.f);
        int p = c - 1;
        for (;;) {
            // warp 0: scan up to 8 flags in one round trip
            if (tid < 32) {
                const int lane = tid;
                const int pp = p - lane;
                unsigned f = 0;
                if (lane < LB_W && pp >= 0) f = ld_acq(&g_flag[b * NC_ + pp]);
                unsigned m1 = __ballot_sync(0xffffffffu, f >= 1u) & ((1u << LB_W) - 1u);
                unsigned m2 = __ballot_sync(0xffffffffu, f == 2u) & ((1u << LB_W) - 1u);
                if (lane == 0) {
                    unsigned gap = (~m1) & ((1u << LB_W) - 1u);
                    int navail = gap ? (__ffs(gap) - 1) : LB_W;   // consecutive published
                    int linc   = m2 ? (__ffs(m2) - 1) : LB_W;     // first inclusive
                    if (linc < navail) { sh_n = linc; sh_inc = 1; }
                    else               { sh_n = navail; sh_inc = 0; }
                }
            }
            __syncthreads();
            const int n  = sh_n;
            const int inc = sh_inc;
            __syncthreads();                  // smem safe for next round

            if (n == 0 && !inc) { __nanosleep(64); continue; }

            // batched aggregate loads (predicated, unrolled -> MLP)
            float4 Apb[LB_W], Upb[LB_W], Xv;
            #pragma unroll
            for (int j = 0; j < LB_W; ++j) {
                if (j < n) {
                    const int pi = ((b * NC_ + (p - j)) * D_ + d) >> 2;
                    Apb[j] = gA4[pi];
                    Upb[j] = gU4[pi];
                }
            }
            if (inc) Xv = gX4[((b * NC_ + (p - n)) * D_ + d) >> 2];

            #pragma unroll
            for (int j = 0; j < LB_W; ++j) {
                if (j < n) {
                    Us = f4_fma(As, Upb[j], Us);
                    As = f4_mul(As, Apb[j]);
                }
            }
            if (inc) { x_in = f4_fma(As, Xv, Us); break; }
            p -= n;
        }

        // ---- Phase 3: publish inclusive (from registers; unblocks successors early)
        gX4[si] = f4_fma(A, x_in, U);
        __syncthreads();
        if (tid == 0) { __threadfence(); st_rel(&g_flag[b * NC_ + c], 2u); }
    }

    // ---- Phase 4: re-stream chunk (L2-warm) and write outputs
    float4* __restrict__ op = reinterpret_cast<float4*>(out) + base;
    float4 x = x_in;
    float4 x0v;
    if (c == 0) x0v = reinterpret_cast<const float4*>(x0)[(b * D_ + d) >> 2];
    #pragma unroll
    for (int t = 0; t < L_; ++t) {
        float4 av = ap[(long)t * (D_ / 4)];
        float4 uv = up[(long)t * (D_ / 4)];
        if (c == 0 && t == 0) uv = f4_fma(av, x0v, uv);
        x = f4_fma(av, x, uv);
        op[(long)t * (D_ / 4)] = x;
    }
}

extern "C" void kernel_launch(void* const* d_in, const int* in_sizes, int n_in,
                              void* d_out, int out_size) {
    const float* x0 = (const float*)d_in[0];
    const float* a  = (const float*)d_in[1];
    const float* u  = (const float*)d_in[2];
    float* out = (float*)d_out;

    k_reset<<<(NBLK + 255) / 256, 256>>>();
    k_scan<<<NBLK, TPB>>>(a, u, x0, out);
}